// round 12
// baseline (speedup 1.0000x reference)
#include <cuda_runtime.h>
#include <cuda_bf16.h>
#include <cstdint>
#include <math.h>

// Problem dims
#define NB   4
#define SEQ  1024
#define MDIM 1024
#define HH   16
#define DD   64
#define FF   4096
#define ROWS (NB*SEQ)          // 4096
#define EPS  1e-5f

// ---------------- scratch (device globals; no allocation allowed) -------------
__device__ float g_wqkv_s[MDIM*3*MDIM];   // repacked [m][3072]
__device__ float g_bqkv_s[3*MDIM];
__device__ float g_wq_c [MDIM*MDIM];
__device__ float g_wkv_c[MDIM*2*MDIM];
__device__ float g_bkv_c[2*MDIM];

// packed (fragment-layout, tf32-rounded) weights
__device__ float g_p_wqkv[MDIM*3*MDIM];
__device__ float g_p_wqc [MDIM*MDIM];
__device__ float g_p_wkvc[MDIM*2*MDIM];
__device__ float g_p_wos [MDIM*MDIM];
__device__ float g_p_woc [MDIM*MDIM];
__device__ float g_p_w1  [MDIM*FF];
__device__ float g_p_w2  [FF*MDIM];

__device__ float g_qkv [ROWS*3*MDIM];
__device__ float g_qc  [ROWS*MDIM];
__device__ float g_kvc [ROWS*2*MDIM];
__device__ float g_attn[ROWS*MDIM];
__device__ float g_t1  [ROWS*MDIM];
__device__ float g_out2[ROWS*MDIM];
__device__ float g_out4[ROWS*MDIM];
__device__ float g_ffn [ROWS*FF];

// ---------------- helpers -----------------------------------------------------
__device__ __forceinline__ float to_tf32(float x)
{
    asm("cvt.rna.tf32.f32 %0, %0;" : "+f"(x));
    return x;
}

__device__ __forceinline__ void mma_tf32(float* d,
                                         float a0, float a1, float a2, float a3,
                                         float b0, float b1)
{
    asm volatile(
        "mma.sync.aligned.m16n8k8.row.col.f32.tf32.tf32.f32 "
        "{%0,%1,%2,%3}, {%4,%5,%6,%7}, {%8,%9}, {%0,%1,%2,%3};\n"
        : "+f"(d[0]), "+f"(d[1]), "+f"(d[2]), "+f"(d[3])
        : "r"(__float_as_uint(a0)), "r"(__float_as_uint(a1)),
          "r"(__float_as_uint(a2)), "r"(__float_as_uint(a3)),
          "r"(__float_as_uint(b0)), "r"(__float_as_uint(b1)));
}

__device__ __forceinline__ uint32_t smem_u32(const void* p)
{
    uint32_t a;
    asm("{ .reg .u64 t; cvta.to.shared.u64 t, %1; cvt.u32.u64 %0, t; }"
        : "=r"(a) : "l"(p));
    return a;
}

__device__ __forceinline__ void cp16(uint32_t dst, const void* src)
{
    asm volatile("cp.async.cg.shared.global [%0], [%1], 16;"
                 :: "r"(dst), "l"(src));
}
#define CP_COMMIT() asm volatile("cp.async.commit_group;" ::: "memory")
#define CP_WAIT2()  asm volatile("cp.async.wait_group 2;" ::: "memory")

// ---------------- weight repack (attention weights -> [m][N]) -----------------
__global__ void repack_all_kernel(const float* __restrict__ Wq_s, const float* __restrict__ Wk_s,
                                  const float* __restrict__ Wv_s, const float* __restrict__ Wq_c,
                                  const float* __restrict__ Wk_c, const float* __restrict__ Wv_c,
                                  float* __restrict__ wqkv_s, float* __restrict__ wq_c,
                                  float* __restrict__ wkv_c)
{
    const float* W; float* dst; int stride, off;
    switch (blockIdx.y) {
        case 0: W = Wq_s; dst = wqkv_s; stride = 3*MDIM; off = 0;      break;
        case 1: W = Wk_s; dst = wqkv_s; stride = 3*MDIM; off = MDIM;   break;
        case 2: W = Wv_s; dst = wqkv_s; stride = 3*MDIM; off = 2*MDIM; break;
        case 3: W = Wq_c; dst = wq_c;   stride = MDIM;   off = 0;      break;
        case 4: W = Wk_c; dst = wkv_c;  stride = 2*MDIM; off = 0;      break;
        default:W = Wv_c; dst = wkv_c;  stride = 2*MDIM; off = MDIM;   break;
    }
    int idx = blockIdx.x * 256 + threadIdx.x;
    int d = idx & 63;
    int m = (idx >> 6) & (MDIM-1);
    int h = idx >> 16;
    dst[m*stride + off + h*64 + d] = W[idx];
}

// ---------------- pack all 7 W[K][N] into fragment layout (ONE launch) --------
__global__ void packW_all_kernel(const float* __restrict__ wqkv, const float* __restrict__ wqc,
                                 const float* __restrict__ wkvc, const float* __restrict__ wos,
                                 const float* __restrict__ woc, const float* __restrict__ w1,
                                 const float* __restrict__ w2,
                                 float* __restrict__ p_wqkv, float* __restrict__ p_wqc,
                                 float* __restrict__ p_wkvc, float* __restrict__ p_wos,
                                 float* __restrict__ p_woc, float* __restrict__ p_w1,
                                 float* __restrict__ p_w2)
{
    const float* W; float* Wp; int K, N;
    switch (blockIdx.y) {
        case 0: W = wqkv; Wp = p_wqkv; K = MDIM; N = 3*MDIM; break;
        case 1: W = wqc;  Wp = p_wqc;  K = MDIM; N = MDIM;   break;
        case 2: W = wkvc; Wp = p_wkvc; K = MDIM; N = 2*MDIM; break;
        case 3: W = wos;  Wp = p_wos;  K = MDIM; N = MDIM;   break;
        case 4: W = woc;  Wp = p_woc;  K = MDIM; N = MDIM;   break;
        case 5: W = w1;   Wp = p_w1;   K = MDIM; N = FF;     break;
        default:W = w2;   Wp = p_w2;   K = FF;   N = MDIM;   break;
    }
    int idx = blockIdx.x * 256 + threadIdx.x;
    if (idx >= (K >> 2) * N) return;
    int j = idx & 3;
    int q = idx >> 2;
    int n = q % N;
    int kb = q / N;
    int kb16 = kb * 16 + (j ^ (n & 3));
    float4 v;
    v.x = to_tf32(W[(size_t)(kb16 +  0) * N + n]);
    v.y = to_tf32(W[(size_t)(kb16 +  4) * N + n]);
    v.z = to_tf32(W[(size_t)(kb16 +  8) * N + n]);
    v.w = to_tf32(W[(size_t)(kb16 + 12) * N + n]);
    *(float4*)&Wp[(size_t)idx * 4] = v;
}

// ===================== cp.async pipelined TF32 GEMM ===========================
// CTA 128x256, BK=16, 4 stages, 512 threads (16 warps, 32x64 warp tile).
#define STG_BYTES 26624           // 10240 (A, 80B rows) + 16384 (B)
#define GEMM_SMEM (4*STG_BYTES)   // 106496

__global__ __launch_bounds__(512, 1)
void tf32gemm_kernel(const float* __restrict__ A, const float* __restrict__ Bp,
                     const float* __restrict__ bias, const float* __restrict__ res,
                     float* __restrict__ C, int Kd, int Nn, int relu)
{
    extern __shared__ char smraw[];
    const uint32_t smb = smem_u32(smraw);

    const int tid  = threadIdx.x;
    const int lane = tid & 31;
    const int g    = lane >> 2;
    const int c    = lane & 3;
    const int warp = tid >> 5;            // 0..15
    const int wm   = (warp >> 2) * 32;    // 0,32,64,96
    const int wn   = (warp & 3) * 64;     // 0..192
    const int bm   = blockIdx.y * 128;
    const int bn   = blockIdx.x * 256;

    // A loader: one cp16/thread: row = tid>>2, quarter = tid&3
    const int arow = tid >> 2;
    const int aq   = tid & 3;
    const float* Asrc0 = A + (size_t)(bm + arow) * Kd + aq * 4;
    // B loader: two cp16/thread: n = tid>>1, half = tid&1 (32B each)
    const int bnn  = tid >> 1;
    const int bh   = tid & 1;
    const float* Bsrc0 = Bp + ((size_t)bn + bnn) * 16 + bh * 8;

    float acc[2][8][4];
#pragma unroll
    for (int i = 0; i < 2; i++)
#pragma unroll
        for (int t = 0; t < 8; t++)
#pragma unroll
            for (int r = 0; r < 4; r++) acc[i][t][r] = 0.f;

    const int iters = Kd >> 4;

    auto issue = [&](int s) {
        uint32_t base = smb + (s & 3) * STG_BYTES;
        cp16(base + arow * 80 + aq * 16, Asrc0 + s * 16);
        uint32_t bdst = base + 10240 + bnn * 64 + bh * 32;
        const float* bsrc = Bsrc0 + (size_t)s * Nn * 16;
        cp16(bdst,      bsrc);
        cp16(bdst + 16, bsrc + 4);
    };

#pragma unroll
    for (int s = 0; s < 3; s++) {
        if (s < iters) issue(s);
        CP_COMMIT();
    }

    const char* smc = (const char*)smraw;
    const uint32_t bchunk = ((uint32_t)(c ^ (g & 3))) << 4;

    for (int it = 0; it < iters; ++it) {
        CP_WAIT2();
        __syncthreads();
        if (it + 3 < iters) issue(it + 3);
        CP_COMMIT();

        const char* sA = smc + (it & 3) * STG_BYTES;
        const char* sB = sA + 10240;

        float4 bf[8];
#pragma unroll
        for (int t = 0; t < 8; t++)
            bf[t] = *(const float4*)(sB + (wn + t*8 + g) * 64 + bchunk);

#pragma unroll
        for (int i = 0; i < 2; i++) {
            int r0 = wm + i*16 + g;
            const float* a0p = (const float*)(sA + r0 * 80);
            const float* a1p = (const float*)(sA + (r0 + 8) * 80);
            float aL[4], aH[4];
#pragma unroll
            for (int j = 0; j < 4; j++) {
                aL[j] = a0p[c + 4*j];
                aH[j] = a1p[c + 4*j];
            }
#pragma unroll
            for (int t = 0; t < 8; t++) {
                mma_tf32(acc[i][t], aL[0], aH[0], aL[1], aH[1], bf[t].x, bf[t].y);
                mma_tf32(acc[i][t], aL[2], aH[2], aL[3], aH[3], bf[t].z, bf[t].w);
            }
        }
    }

#pragma unroll
    for (int i = 0; i < 2; i++) {
        int r0 = bm + wm + i*16 + g;
#pragma unroll
        for (int t = 0; t < 8; t++) {
            int col = bn + wn + t*8 + 2*c;
            float2 bv = *(const float2*)&bias[col];
            float v0 = acc[i][t][0] + bv.x;
            float v1 = acc[i][t][1] + bv.y;
            float v2 = acc[i][t][2] + bv.x;
            float v3 = acc[i][t][3] + bv.y;
            size_t o0 = (size_t)r0 * Nn + col;
            size_t o1 = (size_t)(r0 + 8) * Nn + col;
            if (res) {
                float2 r0v = *(const float2*)&res[o0];
                float2 r1v = *(const float2*)&res[o1];
                v0 += r0v.x; v1 += r0v.y; v2 += r1v.x; v3 += r1v.y;
            }
            if (relu) {
                v0 = fmaxf(v0, 0.f); v1 = fmaxf(v1, 0.f);
                v2 = fmaxf(v2, 0.f); v3 = fmaxf(v3, 0.f);
            }
            float2 w0 = {v0, v1};
            float2 w1 = {v2, v3};
            *(float2*)&C[o0] = w0;
            *(float2*)&C[o1] = w1;
        }
    }
}

// ===================== TF32 tensor-core flash attention =======================
// 128 q-rows per CTA (8 warps x 16 rows), key blocks of 64, D=64.
#define ATT_SMEM 98304

__global__ __launch_bounds__(256)
void tc_attn_kernel(const float* __restrict__ Qb, int sQ,
                    const float* __restrict__ Kb, int sK,
                    const float* __restrict__ Vb, int sV,
                    float* __restrict__ Ob, int causal)
{
    extern __shared__ float sm[];
    float* Qs = sm;            // [4][128][16]  (8192)
    float* Ks = sm + 8192;     // [4][64][16]   (4096)
    float* Vs = sm + 12288;    // [4][64][16]   (4096)
    float* Ps = sm + 16384;    // [warp][4][16][16] (8192)

    const int qb   = blockIdx.x;
    const int nh   = blockIdx.y;
    const int n    = nh >> 4, h = nh & 15;
    const int tid  = threadIdx.x;
    const int lane = tid & 31;
    const int warp = tid >> 5;
    const int g    = lane >> 2;
    const int c    = lane & 3;
    const int wm   = warp * 16;
    const int qrow0 = n*SEQ + qb*128;
    const float scale = 0.125f;
    const int fcol = (4*c) ^ ((g & 3) << 2);

#pragma unroll
    for (int i = 0; i < 8; i++) {
        int idx = tid + i*256;
        int r   = idx >> 4;
        int d0  = (idx & 15) * 4;
        float4 v = *(const float4*)&Qb[(size_t)(qrow0 + r)*sQ + h*64 + d0];
        int j    = d0 >> 4;
        int base = (d0 & 15) >> 2;
        int swz  = (r & 3) << 2;
        float* dst = &Qs[j*2048 + r*16];
        dst[(0*4 + base) ^ swz] = to_tf32(v.x * scale);
        dst[(1*4 + base) ^ swz] = to_tf32(v.y * scale);
        dst[(2*4 + base) ^ swz] = to_tf32(v.z * scale);
        dst[(3*4 + base) ^ swz] = to_tf32(v.w * scale);
    }
    __syncthreads();

    float4 qa[4][2];
#pragma unroll
    for (int j = 0; j < 4; j++) {
        qa[j][0] = *(const float4*)&Qs[j*2048 + (wm + g)*16 + fcol];
        qa[j][1] = *(const float4*)&Qs[j*2048 + (wm + 8 + g)*16 + fcol];
    }

    float m_lo = -1e30f, m_hi = -1e30f, l_lo = 0.f, l_hi = 0.f;
    float oacc[8][4];
#pragma unroll
    for (int t = 0; t < 8; t++)
#pragma unroll
        for (int r = 0; r < 4; r++) oacc[t][r] = 0.f;

    const int row_lo = qrow0 + wm + g;
    const int row_hi = row_lo + 8;
    const int nkb = causal ? (2*qb + 2) : (SEQ/64);

    for (int kb = 0; kb < nkb; kb++) {
        const int krow0 = n*SEQ + kb*64;
        __syncthreads();

#pragma unroll
        for (int i = 0; i < 4; i++) {
            int idx = tid + i*256;
            int r   = idx >> 4;
            int d0  = (idx & 15) * 4;
            float4 kv = *(const float4*)&Kb[(size_t)(krow0 + r)*sK + h*64 + d0];
            int j    = d0 >> 4;
            int base = (d0 & 15) >> 2;
            int swz  = (r & 3) << 2;
            float* dst = &Ks[j*1024 + r*16];
            dst[(0*4 + base) ^ swz] = to_tf32(kv.x);
            dst[(1*4 + base) ^ swz] = to_tf32(kv.y);
            dst[(2*4 + base) ^ swz] = to_tf32(kv.z);
            dst[(3*4 + base) ^ swz] = to_tf32(kv.w);

            float4 vv = *(const float4*)&Vb[(size_t)(krow0 + r)*sV + h*64 + d0];
            int jk    = r >> 4;
            int k16   = r & 15;
            int kperm = (k16 & 3)*4 + (k16 >> 2);
            float* vdst = &Vs[jk*1024];
            vdst[(d0+0)*16 + (kperm ^  0)] = to_tf32(vv.x);
            vdst[(d0+1)*16 + (kperm ^  4)] = to_tf32(vv.y);
            vdst[(d0+2)*16 + (kperm ^  8)] = to_tf32(vv.z);
            vdst[(d0+3)*16 + (kperm ^ 12)] = to_tf32(vv.w);
        }
        __syncthreads();

        const bool active = !(causal && kb == 2*qb + 1 && warp < 4);
        if (active) {
            float sacc[8][4];
#pragma unroll
            for (int t = 0; t < 8; t++)
#pragma unroll
                for (int r = 0; r < 4; r++) sacc[t][r] = 0.f;

#pragma unroll
            for (int j = 0; j < 4; j++) {
                float4 a0v = qa[j][0], a1v = qa[j][1];
#pragma unroll
                for (int t = 0; t < 8; t++) {
                    float4 bf = *(const float4*)&Ks[j*1024 + (t*8 + g)*16 + fcol];
                    mma_tf32(sacc[t], a0v.x, a1v.x, a0v.y, a1v.y, bf.x, bf.y);
                    mma_tf32(sacc[t], a0v.z, a1v.z, a0v.w, a1v.w, bf.z, bf.w);
                }
            }

            if (causal && kb >= 2*qb) {
#pragma unroll
                for (int t = 0; t < 8; t++) {
                    int col0 = krow0 + t*8 + 2*c;
                    if (col0     > row_lo) sacc[t][0] = -1e30f;
                    if (col0 + 1 > row_lo) sacc[t][1] = -1e30f;
                    if (col0     > row_hi) sacc[t][2] = -1e30f;
                    if (col0 + 1 > row_hi) sacc[t][3] = -1e30f;
                }
            }

            float mx_lo = -1e30f, mx_hi = -1e30f;
#pragma unroll
            for (int t = 0; t < 8; t++) {
                mx_lo = fmaxf(mx_lo, fmaxf(sacc[t][0], sacc[t][1]));
                mx_hi = fmaxf(mx_hi, fmaxf(sacc[t][2], sacc[t][3]));
            }
            mx_lo = fmaxf(mx_lo, __shfl_xor_sync(0xffffffffu, mx_lo, 1));
            mx_lo = fmaxf(mx_lo, __shfl_xor_sync(0xffffffffu, mx_lo, 2));
            mx_hi = fmaxf(mx_hi, __shfl_xor_sync(0xffffffffu, mx_hi, 1));
            mx_hi = fmaxf(mx_hi, __shfl_xor_sync(0xffffffffu, mx_hi, 2));

            float mn_lo = fmaxf(m_lo, mx_lo);
            float mn_hi = fmaxf(m_hi, mx_hi);
            float al_lo = __expf(m_lo - mn_lo);
            float al_hi = __expf(m_hi - mn_hi);

            float sum_lo = 0.f, sum_hi = 0.f;
#pragma unroll
            for (int t = 0; t < 8; t++) {
                sacc[t][0] = __expf(sacc[t][0] - mn_lo);
                sacc[t][1] = __expf(sacc[t][1] - mn_lo);
                sacc[t][2] = __expf(sacc[t][2] - mn_hi);
                sacc[t][3] = __expf(sacc[t][3] - mn_hi);
                sum_lo += sacc[t][0] + sacc[t][1];
                sum_hi += sacc[t][2] + sacc[t][3];
            }
            sum_lo += __shfl_xor_sync(0xffffffffu, sum_lo, 1);
            sum_lo += __shfl_xor_sync(0xffffffffu, sum_lo, 2);
            sum_hi += __shfl_xor_sync(0xffffffffu, sum_hi, 1);
            sum_hi += __shfl_xor_sync(0xffffffffu, sum_hi, 2);

            l_lo = l_lo * al_lo + sum_lo;
            l_hi = l_hi * al_hi + sum_hi;
            m_lo = mn_lo;
            m_hi = mn_hi;
#pragma unroll
            for (int t = 0; t < 8; t++) {
                oacc[t][0] *= al_lo; oacc[t][1] *= al_lo;
                oacc[t][2] *= al_hi; oacc[t][3] *= al_hi;
            }

            {
                float* pw = &Ps[warp * 1024];
                const int swz = (g & 3) << 2;
#pragma unroll
                for (int t = 0; t < 8; t++) {
                    int kc  = t*8 + 2*c;
                    int jk  = kc >> 4;
                    int k16 = kc & 15;
                    int pp0  = ((k16 & 3) << 2) | (k16 >> 2);
                    int pp1  = (((k16+1) & 3) << 2) | ((k16+1) >> 2);
                    float* base_lo = &pw[jk*256 + g*16];
                    float* base_hi = &pw[jk*256 + (g+8)*16];
                    base_lo[pp0 ^ swz] = to_tf32(sacc[t][0]);
                    base_lo[pp1 ^ swz] = to_tf32(sacc[t][1]);
                    base_hi[pp0 ^ swz] = to_tf32(sacc[t][2]);
                    base_hi[pp1 ^ swz] = to_tf32(sacc[t][3]);
                }
            }
            __syncwarp();

            {
                const float* pw = &Ps[warp * 1024];
#pragma unroll
                for (int jk = 0; jk < 4; jk++) {
                    float4 pa0 = *(const float4*)&pw[jk*256 + g*16 + fcol];
                    float4 pa1 = *(const float4*)&pw[jk*256 + (g+8)*16 + fcol];
#pragma unroll
                    for (int t = 0; t < 8; t++) {
                        float4 vf = *(const float4*)&Vs[jk*1024 + (t*8 + g)*16 + fcol];
                        mma_tf32(oacc[t], pa0.x, pa1.x, pa0.y, pa1.y, vf.x, vf.y);
                        mma_tf32(oacc[t], pa0.z, pa1.z, pa0.w, pa1.w, vf.z, vf.w);
                    }
                }
            }
        }
    }

    float inv_lo = 1.f / l_lo;
    float inv_hi = 1.f / l_hi;
#pragma unroll
    for (int t = 0; t < 8; t++) {
        int d = t*8 + 2*c;
        float2 w0 = {oacc[t][0] * inv_lo, oacc[t][1] * inv_lo};
        float2 w1 = {oacc[t][2] * inv_hi, oacc[t][3] * inv_hi};
        *(float2*)&Ob[(size_t)row_lo * MDIM + h*64 + d] = w0;
        *(float2*)&Ob[(size_t)row_hi * MDIM + h*64 + d] = w1;
    }
}

// ---------------- LayerNorm ---------------------------------------------------
__global__ __launch_bounds__(256)
void ln_kernel(const float* __restrict__ X, const float* __restrict__ g,
               const float* __restrict__ b, float* __restrict__ Y)
{
    __shared__ float red[16];
    const int row = blockIdx.x;
    const int tid = threadIdx.x;
    float4 v = ((const float4*)(X + (size_t)row*MDIM))[tid];
    float s  = v.x + v.y + v.z + v.w;
    float sq = v.x*v.x + v.y*v.y + v.z*v.z + v.w*v.w;
#pragma unroll
    for (int off = 16; off > 0; off >>= 1) {
        s  += __shfl_xor_sync(0xffffffffu, s,  off);
        sq += __shfl_xor_sync(0xffffffffu, sq, off);
    }
    int wid = tid >> 5;
    if ((tid & 31) == 0) { red[wid] = s; red[8 + wid] = sq; }
    __syncthreads();
    if (tid < 32) {
        float ss = (tid < 8) ? red[tid] : 0.f;
        float qq = (tid < 8) ? red[8 + tid] : 0.f;
#pragma unroll
        for (int off = 4; off > 0; off >>= 1) {
            ss += __shfl_xor_sync(0xffffffffu, ss, off);
            qq += __shfl_xor_sync(0xffffffffu, qq, off);
        }
        if (tid == 0) { red[0] = ss; red[1] = qq; }
    }
    __syncthreads();
    float mu  = red[0] * (1.f/1024.f);
    float var = red[1] * (1.f/1024.f) - mu*mu;
    float rstd = rsqrtf(var + EPS);
    float4 gv = ((const float4*)g)[tid];
    float4 bv = ((const float4*)b)[tid];
    float4 y;
    y.x = (v.x - mu)*rstd*gv.x + bv.x;
    y.y = (v.y - mu)*rstd*gv.y + bv.y;
    y.z = (v.z - mu)*rstd*gv.z + bv.z;
    y.w = (v.w - mu)*rstd*gv.w + bv.w;
    ((float4*)(Y + (size_t)row*MDIM))[tid] = y;
}

// ---------------- launch ------------------------------------------------------
static void sgemm(const float* A, const float* Bp, const float* bias,
                  const float* res, float* C, int Kd, int Nn, int relu)
{
    dim3 grid(Nn/256, ROWS/128);
    tf32gemm_kernel<<<grid, 512, GEMM_SMEM>>>(A, Bp, bias, res, C, Kd, Nn, relu);
}

extern "C" void kernel_launch(void* const* d_in, const int* in_sizes, int n_in,
                              void* d_out, int out_size)
{
    const float* dec  = (const float*)d_in[0];
    const float* enc  = (const float*)d_in[1];
    const float* Wq_s = (const float*)d_in[3];
    const float* bq_s = (const float*)d_in[4];
    const float* Wk_s = (const float*)d_in[5];
    const float* bk_s = (const float*)d_in[6];
    const float* Wv_s = (const float*)d_in[7];
    const float* bv_s = (const float*)d_in[8];
    const float* Wo_s = (const float*)d_in[9];
    const float* bo_s = (const float*)d_in[10];
    const float* Wq_c = (const float*)d_in[11];
    const float* bq_c = (const float*)d_in[12];
    const float* Wk_c = (const float*)d_in[13];
    const float* bk_c = (const float*)d_in[14];
    const float* Wv_c = (const float*)d_in[15];
    const float* bv_c = (const float*)d_in[16];
    const float* Wo_c = (const float*)d_in[17];
    const float* bo_c = (const float*)d_in[18];
    const float* W1   = (const float*)d_in[19];
    const float* b1   = (const float*)d_in[20];
    const float* W2   = (const float*)d_in[21];
    const float* b2   = (const float*)d_in[22];
    const float* g1   = (const float*)d_in[23];
    const float* be1  = (const float*)d_in[24];
    const float* g2   = (const float*)d_in[25];
    const float* be2  = (const float*)d_in[26];
    const float* g3   = (const float*)d_in[27];
    const float* be3  = (const float*)d_in[28];
    float* out = (float*)d_out;

    float *wqkv_s, *bqkv_s, *wq_c, *wkv_c, *bkv_c;
    float *p_wqkv, *p_wqc, *p_wkvc, *p_wos, *p_woc, *p_w1, *p_w2;
    float *qkv, *qc, *kvc, *attn, *t1, *out2, *out4, *ffn;
    cudaGetSymbolAddress((void**)&wqkv_s, g_wqkv_s);
    cudaGetSymbolAddress((void**)&bqkv_s, g_bqkv_s);
    cudaGetSymbolAddress((void**)&wq_c,   g_wq_c);
    cudaGetSymbolAddress((void**)&wkv_c,  g_wkv_c);
    cudaGetSymbolAddress((void**)&bkv_c,  g_bkv_c);
    cudaGetSymbolAddress((void**)&p_wqkv, g_p_wqkv);
    cudaGetSymbolAddress((void**)&p_wqc,  g_p_wqc);
    cudaGetSymbolAddress((void**)&p_wkvc, g_p_wkvc);
    cudaGetSymbolAddress((void**)&p_wos,  g_p_wos);
    cudaGetSymbolAddress((void**)&p_woc,  g_p_woc);
    cudaGetSymbolAddress((void**)&p_w1,   g_p_w1);
    cudaGetSymbolAddress((void**)&p_w2,   g_p_w2);
    cudaGetSymbolAddress((void**)&qkv,    g_qkv);
    cudaGetSymbolAddress((void**)&qc,     g_qc);
    cudaGetSymbolAddress((void**)&kvc,    g_kvc);
    cudaGetSymbolAddress((void**)&attn,   g_attn);
    cudaGetSymbolAddress((void**)&t1,     g_t1);
    cudaGetSymbolAddress((void**)&out2,   g_out2);
    cudaGetSymbolAddress((void**)&out4,   g_out4);
    cudaGetSymbolAddress((void**)&ffn,    g_ffn);

    cudaFuncSetAttribute(tc_attn_kernel, cudaFuncAttributeMaxDynamicSharedMemorySize, ATT_SMEM);
    cudaFuncSetAttribute(tf32gemm_kernel, cudaFuncAttributeMaxDynamicSharedMemorySize, GEMM_SMEM);

    // 1: repack attention weights to [m][N]
    {
        dim3 grid((HH*MDIM*DD)/256, 6);
        repack_all_kernel<<<grid, 256>>>(Wq_s, Wk_s, Wv_s, Wq_c, Wk_c, Wv_c,
                                         wqkv_s, wq_c, wkv_c);
    }
    // 2: pack all weights into fragment layout (one launch)
    {
        dim3 grid((MDIM*FF/4 + 255)/256, 7);
        packW_all_kernel<<<grid, 256>>>(wqkv_s, wq_c, wkv_c, Wo_s, Wo_c, W1, W2,
                                        p_wqkv, p_wqc, p_wkvc, p_wos, p_woc, p_w1, p_w2);
    }
    // concat biases
    cudaMemcpyAsync(bqkv_s,          bq_s, MDIM*sizeof(float), cudaMemcpyDeviceToDevice);
    cudaMemcpyAsync(bqkv_s + MDIM,   bk_s, MDIM*sizeof(float), cudaMemcpyDeviceToDevice);
    cudaMemcpyAsync(bqkv_s + 2*MDIM, bv_s, MDIM*sizeof(float), cudaMemcpyDeviceToDevice);
    cudaMemcpyAsync(bkv_c,           bk_c, MDIM*sizeof(float), cudaMemcpyDeviceToDevice);
    cudaMemcpyAsync(bkv_c + MDIM,    bv_c, MDIM*sizeof(float), cudaMemcpyDeviceToDevice);

    // 3: self QKV gemm
    sgemm(dec, p_wqkv, bqkv_s, nullptr, qkv, MDIM, 3*MDIM, 0);
    // 4: cross KV gemm
    sgemm(enc, p_wkvc, bkv_c, nullptr, kvc, MDIM, 2*MDIM, 0);
    // 5: self attention
    {
        dim3 grid(SEQ/128, NB*HH);
        tc_attn_kernel<<<grid, 256, ATT_SMEM>>>(qkv, 3*MDIM,
                                                qkv + MDIM, 3*MDIM,
                                                qkv + 2*MDIM, 3*MDIM,
                                                attn, 1);
    }
    // 6: Wo_s gemm  <-- ncu profiles this launch
    sgemm(attn, p_wos, bo_s, dec, t1, MDIM, MDIM, 0);
    ln_kernel<<<ROWS, 256>>>(t1, g1, be1, out2);

    // ---- cross-attention block ----
    sgemm(out2, p_wqc, bq_c, nullptr, qc, MDIM, MDIM, 0);
    {
        dim3 grid(SEQ/128, NB*HH);
        tc_attn_kernel<<<grid, 256, ATT_SMEM>>>(qc, MDIM,
                                                kvc, 2*MDIM,
                                                kvc + MDIM, 2*MDIM,
                                                attn, 0);
    }
    sgemm(attn, p_woc, bo_c, out2, t1, MDIM, MDIM, 0);
    ln_kernel<<<ROWS, 256>>>(t1, g2, be2, out4);

    // ---- feedforward block ----
    sgemm(out4, p_w1, b1, nullptr, ffn, MDIM, FF, 1);
    sgemm(ffn, p_w2, b2, out4, t1, FF, MDIM, 0);
    ln_kernel<<<ROWS, 256>>>(t1, g3, be3, out);
}

// round 14
// speedup vs baseline: 1.4861x; 1.4861x over previous
#include <cuda_runtime.h>
#include <cuda_bf16.h>
#include <cstdint>
#include <math.h>

// Problem dims
#define NB   4
#define SEQ  1024
#define MDIM 1024
#define HH   16
#define DD   64
#define FF   4096
#define ROWS (NB*SEQ)          // 4096
#define EPS  1e-5f

// ---------------- scratch (device globals; no allocation allowed) -------------
__device__ float g_wqkv_s[MDIM*3*MDIM];   // repacked [m][3072]
__device__ float g_bqkv_s[3*MDIM];
__device__ float g_wq_c [MDIM*MDIM];
__device__ float g_wkv_c[MDIM*2*MDIM];
__device__ float g_bkv_c[2*MDIM];

// packed (fragment-layout, tf32-rounded) weights
__device__ float g_p_wqkv[MDIM*3*MDIM];
__device__ float g_p_wqc [MDIM*MDIM];
__device__ float g_p_wkvc[MDIM*2*MDIM];
__device__ float g_p_wos [MDIM*MDIM];
__device__ float g_p_woc [MDIM*MDIM];
__device__ float g_p_w1  [MDIM*FF];
__device__ float g_p_w2  [FF*MDIM];

__device__ float g_qkv [ROWS*3*MDIM];
__device__ float g_qc  [ROWS*MDIM];
__device__ float g_kvc [ROWS*2*MDIM];
__device__ float g_attn[ROWS*MDIM];
__device__ float g_t1  [ROWS*MDIM];
__device__ float g_out2[ROWS*MDIM];
__device__ float g_out4[ROWS*MDIM];
__device__ float g_ffn [ROWS*FF];

// ---------------- helpers -----------------------------------------------------
__device__ __forceinline__ float to_tf32(float x)
{
    asm("cvt.rna.tf32.f32 %0, %0;" : "+f"(x));
    return x;
}

__device__ __forceinline__ void mma_tf32(float* d,
                                         float a0, float a1, float a2, float a3,
                                         float b0, float b1)
{
    asm volatile(
        "mma.sync.aligned.m16n8k8.row.col.f32.tf32.tf32.f32 "
        "{%0,%1,%2,%3}, {%4,%5,%6,%7}, {%8,%9}, {%0,%1,%2,%3};\n"
        : "+f"(d[0]), "+f"(d[1]), "+f"(d[2]), "+f"(d[3])
        : "r"(__float_as_uint(a0)), "r"(__float_as_uint(a1)),
          "r"(__float_as_uint(a2)), "r"(__float_as_uint(a3)),
          "r"(__float_as_uint(b0)), "r"(__float_as_uint(b1)));
}

__device__ __forceinline__ uint32_t smem_u32(const void* p)
{
    uint32_t a;
    asm("{ .reg .u64 t; cvta.to.shared.u64 t, %1; cvt.u32.u64 %0, t; }"
        : "=r"(a) : "l"(p));
    return a;
}

__device__ __forceinline__ void cp16(uint32_t dst, const void* src)
{
    asm volatile("cp.async.cg.shared.global [%0], [%1], 16;"
                 :: "r"(dst), "l"(src));
}
#define CP_COMMIT() asm volatile("cp.async.commit_group;" ::: "memory")
#define CP_WAIT2()  asm volatile("cp.async.wait_group 2;" ::: "memory")

// ---------------- weight repack (attention weights -> [m][N]) -----------------
__global__ void repack_all_kernel(const float* __restrict__ Wq_s, const float* __restrict__ Wk_s,
                                  const float* __restrict__ Wv_s, const float* __restrict__ Wq_c,
                                  const float* __restrict__ Wk_c, const float* __restrict__ Wv_c,
                                  float* __restrict__ wqkv_s, float* __restrict__ wq_c,
                                  float* __restrict__ wkv_c)
{
    const float* W; float* dst; int stride, off;
    switch (blockIdx.y) {
        case 0: W = Wq_s; dst = wqkv_s; stride = 3*MDIM; off = 0;      break;
        case 1: W = Wk_s; dst = wqkv_s; stride = 3*MDIM; off = MDIM;   break;
        case 2: W = Wv_s; dst = wqkv_s; stride = 3*MDIM; off = 2*MDIM; break;
        case 3: W = Wq_c; dst = wq_c;   stride = MDIM;   off = 0;      break;
        case 4: W = Wk_c; dst = wkv_c;  stride = 2*MDIM; off = 0;      break;
        default:W = Wv_c; dst = wkv_c;  stride = 2*MDIM; off = MDIM;   break;
    }
    int idx = blockIdx.x * 256 + threadIdx.x;
    int d = idx & 63;
    int m = (idx >> 6) & (MDIM-1);
    int h = idx >> 16;
    dst[m*stride + off + h*64 + d] = W[idx];
}

// ---------------- pack all 7 W[K][N] into fragment layout (ONE launch) --------
__global__ void packW_all_kernel(const float* __restrict__ wqkv, const float* __restrict__ wqc,
                                 const float* __restrict__ wkvc, const float* __restrict__ wos,
                                 const float* __restrict__ woc, const float* __restrict__ w1,
                                 const float* __restrict__ w2,
                                 float* __restrict__ p_wqkv, float* __restrict__ p_wqc,
                                 float* __restrict__ p_wkvc, float* __restrict__ p_wos,
                                 float* __restrict__ p_woc, float* __restrict__ p_w1,
                                 float* __restrict__ p_w2)
{
    const float* W; float* Wp; int K, N;
    switch (blockIdx.y) {
        case 0: W = wqkv; Wp = p_wqkv; K = MDIM; N = 3*MDIM; break;
        case 1: W = wqc;  Wp = p_wqc;  K = MDIM; N = MDIM;   break;
        case 2: W = wkvc; Wp = p_wkvc; K = MDIM; N = 2*MDIM; break;
        case 3: W = wos;  Wp = p_wos;  K = MDIM; N = MDIM;   break;
        case 4: W = woc;  Wp = p_woc;  K = MDIM; N = MDIM;   break;
        case 5: W = w1;   Wp = p_w1;   K = MDIM; N = FF;     break;
        default:W = w2;   Wp = p_w2;   K = FF;   N = MDIM;   break;
    }
    int idx = blockIdx.x * 256 + threadIdx.x;
    if (idx >= (K >> 2) * N) return;
    int j = idx & 3;
    int q = idx >> 2;
    int n = q % N;
    int kb = q / N;
    int kb16 = kb * 16 + (j ^ (n & 3));
    float4 v;
    v.x = to_tf32(W[(size_t)(kb16 +  0) * N + n]);
    v.y = to_tf32(W[(size_t)(kb16 +  4) * N + n]);
    v.z = to_tf32(W[(size_t)(kb16 +  8) * N + n]);
    v.w = to_tf32(W[(size_t)(kb16 + 12) * N + n]);
    *(float4*)&Wp[(size_t)idx * 4] = v;
}

// ===================== cp.async pipelined TF32 GEMM ===========================
// CTA 128x256, BK=16, 4 stages, 512 threads (16 warps, 32x64 warp tile).
// B fragments loaded inline (no bf[] array) to keep regs < 128 (no spills).
#define STG_BYTES 26624           // 10240 (A, 80B rows) + 16384 (B)
#define GEMM_SMEM (4*STG_BYTES)   // 106496

__global__ __launch_bounds__(512, 1)
void tf32gemm_kernel(const float* __restrict__ A, const float* __restrict__ Bp,
                     const float* __restrict__ bias, const float* __restrict__ res,
                     float* __restrict__ C, int Kd, int Nn, int relu)
{
    extern __shared__ char smraw[];
    const uint32_t smb = smem_u32(smraw);

    const int tid  = threadIdx.x;
    const int lane = tid & 31;
    const int g    = lane >> 2;
    const int c    = lane & 3;
    const int warp = tid >> 5;            // 0..15
    const int wm   = (warp >> 2) * 32;    // 0,32,64,96
    const int wn   = (warp & 3) * 64;     // 0..192
    const int bm   = blockIdx.y * 128;
    const int bn   = blockIdx.x * 256;

    // A loader: one cp16/thread
    const int arow = tid >> 2;
    const int aq   = tid & 3;
    const float* Asrc0 = A + (size_t)(bm + arow) * Kd + aq * 4;
    // B loader: two cp16/thread
    const int bnn  = tid >> 1;
    const int bh   = tid & 1;
    const float* Bsrc0 = Bp + ((size_t)bn + bnn) * 16 + bh * 8;

    float acc[2][8][4];
#pragma unroll
    for (int i = 0; i < 2; i++)
#pragma unroll
        for (int t = 0; t < 8; t++)
#pragma unroll
            for (int r = 0; r < 4; r++) acc[i][t][r] = 0.f;

    const int iters = Kd >> 4;

    auto issue = [&](int s) {
        uint32_t base = smb + (s & 3) * STG_BYTES;
        cp16(base + arow * 80 + aq * 16, Asrc0 + s * 16);
        uint32_t bdst = base + 10240 + bnn * 64 + bh * 32;
        const float* bsrc = Bsrc0 + (size_t)s * Nn * 16;
        cp16(bdst,      bsrc);
        cp16(bdst + 16, bsrc + 4);
    };

#pragma unroll
    for (int s = 0; s < 3; s++) {
        if (s < iters) issue(s);
        CP_COMMIT();
    }

    const char* smc = (const char*)smraw;
    const uint32_t bchunk = ((uint32_t)(c ^ (g & 3))) << 4;

    for (int it = 0; it < iters; ++it) {
        CP_WAIT2();
        __syncthreads();
        if (it + 3 < iters) issue(it + 3);
        CP_COMMIT();

        const char* sA = smc + (it & 3) * STG_BYTES;
        const char* sB = sA + 10240;

#pragma unroll
        for (int i = 0; i < 2; i++) {
            int r0 = wm + i*16 + g;
            const float* a0p = (const float*)(sA + r0 * 80);
            const float* a1p = (const float*)(sA + (r0 + 8) * 80);
            float aL[4], aH[4];
#pragma unroll
            for (int j = 0; j < 4; j++) {
                aL[j] = a0p[c + 4*j];
                aH[j] = a1p[c + 4*j];
            }
#pragma unroll
            for (int t = 0; t < 8; t++) {
                float4 bf = *(const float4*)(sB + (wn + t*8 + g) * 64 + bchunk);
                mma_tf32(acc[i][t], aL[0], aH[0], aL[1], aH[1], bf.x, bf.y);
                mma_tf32(acc[i][t], aL[2], aH[2], aL[3], aH[3], bf.z, bf.w);
            }
        }
    }

#pragma unroll
    for (int i = 0; i < 2; i++) {
        int r0 = bm + wm + i*16 + g;
#pragma unroll
        for (int t = 0; t < 8; t++) {
            int col = bn + wn + t*8 + 2*c;
            float2 bv = *(const float2*)&bias[col];
            float v0 = acc[i][t][0] + bv.x;
            float v1 = acc[i][t][1] + bv.y;
            float v2 = acc[i][t][2] + bv.x;
            float v3 = acc[i][t][3] + bv.y;
            size_t o0 = (size_t)r0 * Nn + col;
            size_t o1 = (size_t)(r0 + 8) * Nn + col;
            if (res) {
                float2 r0v = *(const float2*)&res[o0];
                float2 r1v = *(const float2*)&res[o1];
                v0 += r0v.x; v1 += r0v.y; v2 += r1v.x; v3 += r1v.y;
            }
            if (relu) {
                v0 = fmaxf(v0, 0.f); v1 = fmaxf(v1, 0.f);
                v2 = fmaxf(v2, 0.f); v3 = fmaxf(v3, 0.f);
            }
            float2 w0 = {v0, v1};
            float2 w1 = {v2, v3};
            *(float2*)&C[o0] = w0;
            *(float2*)&C[o1] = w1;
        }
    }
}

// ===================== TF32 tensor-core flash attention =======================
// 128 q-rows per CTA (8 warps x 16 rows), key blocks of 64, D=64.
#define ATT_SMEM 98304

__global__ __launch_bounds__(256)
void tc_attn_kernel(const float* __restrict__ Qb, int sQ,
                    const float* __restrict__ Kb, int sK,
                    const float* __restrict__ Vb, int sV,
                    float* __restrict__ Ob, int causal)
{
    extern __shared__ float sm[];
    float* Qs = sm;            // [4][128][16]  (8192)
    float* Ks = sm + 8192;     // [4][64][16]   (4096)
    float* Vs = sm + 12288;    // [4][64][16]   (4096)
    float* Ps = sm + 16384;    // [warp][4][16][16] (8192)

    const int qb   = blockIdx.x;
    const int nh   = blockIdx.y;
    const int n    = nh >> 4, h = nh & 15;
    const int tid  = threadIdx.x;
    const int lane = tid & 31;
    const int warp = tid >> 5;
    const int g    = lane >> 2;
    const int c    = lane & 3;
    const int wm   = warp * 16;
    const int qrow0 = n*SEQ + qb*128;
    const float scale = 0.125f;
    const int fcol = (4*c) ^ ((g & 3) << 2);

#pragma unroll
    for (int i = 0; i < 8; i++) {
        int idx = tid + i*256;
        int r   = idx >> 4;
        int d0  = (idx & 15) * 4;
        float4 v = *(const float4*)&Qb[(size_t)(qrow0 + r)*sQ + h*64 + d0];
        int j    = d0 >> 4;
        int base = (d0 & 15) >> 2;
        int swz  = (r & 3) << 2;
        float* dst = &Qs[j*2048 + r*16];
        dst[(0*4 + base) ^ swz] = to_tf32(v.x * scale);
        dst[(1*4 + base) ^ swz] = to_tf32(v.y * scale);
        dst[(2*4 + base) ^ swz] = to_tf32(v.z * scale);
        dst[(3*4 + base) ^ swz] = to_tf32(v.w * scale);
    }
    __syncthreads();

    float4 qa[4][2];
#pragma unroll
    for (int j = 0; j < 4; j++) {
        qa[j][0] = *(const float4*)&Qs[j*2048 + (wm + g)*16 + fcol];
        qa[j][1] = *(const float4*)&Qs[j*2048 + (wm + 8 + g)*16 + fcol];
    }

    float m_lo = -1e30f, m_hi = -1e30f, l_lo = 0.f, l_hi = 0.f;
    float oacc[8][4];
#pragma unroll
    for (int t = 0; t < 8; t++)
#pragma unroll
        for (int r = 0; r < 4; r++) oacc[t][r] = 0.f;

    const int row_lo = qrow0 + wm + g;
    const int row_hi = row_lo + 8;
    const int nkb = causal ? (2*qb + 2) : (SEQ/64);

    for (int kb = 0; kb < nkb; kb++) {
        const int krow0 = n*SEQ + kb*64;
        __syncthreads();

#pragma unroll
        for (int i = 0; i < 4; i++) {
            int idx = tid + i*256;
            int r   = idx >> 4;
            int d0  = (idx & 15) * 4;
            float4 kv = *(const float4*)&Kb[(size_t)(krow0 + r)*sK + h*64 + d0];
            int j    = d0 >> 4;
            int base = (d0 & 15) >> 2;
            int swz  = (r & 3) << 2;
            float* dst = &Ks[j*1024 + r*16];
            dst[(0*4 + base) ^ swz] = to_tf32(kv.x);
            dst[(1*4 + base) ^ swz] = to_tf32(kv.y);
            dst[(2*4 + base) ^ swz] = to_tf32(kv.z);
            dst[(3*4 + base) ^ swz] = to_tf32(kv.w);

            float4 vv = *(const float4*)&Vb[(size_t)(krow0 + r)*sV + h*64 + d0];
            int jk    = r >> 4;
            int k16   = r & 15;
            int kperm = (k16 & 3)*4 + (k16 >> 2);
            float* vdst = &Vs[jk*1024];
            vdst[(d0+0)*16 + (kperm ^  0)] = to_tf32(vv.x);
            vdst[(d0+1)*16 + (kperm ^  4)] = to_tf32(vv.y);
            vdst[(d0+2)*16 + (kperm ^  8)] = to_tf32(vv.z);
            vdst[(d0+3)*16 + (kperm ^ 12)] = to_tf32(vv.w);
        }
        __syncthreads();

        const bool active = !(causal && kb == 2*qb + 1 && warp < 4);
        if (active) {
            float sacc[8][4];
#pragma unroll
            for (int t = 0; t < 8; t++)
#pragma unroll
                for (int r = 0; r < 4; r++) sacc[t][r] = 0.f;

#pragma unroll
            for (int j = 0; j < 4; j++) {
                float4 a0v = qa[j][0], a1v = qa[j][1];
#pragma unroll
                for (int t = 0; t < 8; t++) {
                    float4 bf = *(const float4*)&Ks[j*1024 + (t*8 + g)*16 + fcol];
                    mma_tf32(sacc[t], a0v.x, a1v.x, a0v.y, a1v.y, bf.x, bf.y);
                    mma_tf32(sacc[t], a0v.z, a1v.z, a0v.w, a1v.w, bf.z, bf.w);
                }
            }

            if (causal && kb >= 2*qb) {
#pragma unroll
                for (int t = 0; t < 8; t++) {
                    int col0 = krow0 + t*8 + 2*c;
                    if (col0     > row_lo) sacc[t][0] = -1e30f;
                    if (col0 + 1 > row_lo) sacc[t][1] = -1e30f;
                    if (col0     > row_hi) sacc[t][2] = -1e30f;
                    if (col0 + 1 > row_hi) sacc[t][3] = -1e30f;
                }
            }

            float mx_lo = -1e30f, mx_hi = -1e30f;
#pragma unroll
            for (int t = 0; t < 8; t++) {
                mx_lo = fmaxf(mx_lo, fmaxf(sacc[t][0], sacc[t][1]));
                mx_hi = fmaxf(mx_hi, fmaxf(sacc[t][2], sacc[t][3]));
            }
            mx_lo = fmaxf(mx_lo, __shfl_xor_sync(0xffffffffu, mx_lo, 1));
            mx_lo = fmaxf(mx_lo, __shfl_xor_sync(0xffffffffu, mx_lo, 2));
            mx_hi = fmaxf(mx_hi, __shfl_xor_sync(0xffffffffu, mx_hi, 1));
            mx_hi = fmaxf(mx_hi, __shfl_xor_sync(0xffffffffu, mx_hi, 2));

            float mn_lo = fmaxf(m_lo, mx_lo);
            float mn_hi = fmaxf(m_hi, mx_hi);
            float al_lo = __expf(m_lo - mn_lo);
            float al_hi = __expf(m_hi - mn_hi);

            float sum_lo = 0.f, sum_hi = 0.f;
#pragma unroll
            for (int t = 0; t < 8; t++) {
                sacc[t][0] = __expf(sacc[t][0] - mn_lo);
                sacc[t][1] = __expf(sacc[t][1] - mn_lo);
                sacc[t][2] = __expf(sacc[t][2] - mn_hi);
                sacc[t][3] = __expf(sacc[t][3] - mn_hi);
                sum_lo += sacc[t][0] + sacc[t][1];
                sum_hi += sacc[t][2] + sacc[t][3];
            }
            sum_lo += __shfl_xor_sync(0xffffffffu, sum_lo, 1);
            sum_lo += __shfl_xor_sync(0xffffffffu, sum_lo, 2);
            sum_hi += __shfl_xor_sync(0xffffffffu, sum_hi, 1);
            sum_hi += __shfl_xor_sync(0xffffffffu, sum_hi, 2);

            l_lo = l_lo * al_lo + sum_lo;
            l_hi = l_hi * al_hi + sum_hi;
            m_lo = mn_lo;
            m_hi = mn_hi;
#pragma unroll
            for (int t = 0; t < 8; t++) {
                oacc[t][0] *= al_lo; oacc[t][1] *= al_lo;
                oacc[t][2] *= al_hi; oacc[t][3] *= al_hi;
            }

            {
                float* pw = &Ps[warp * 1024];
                const int swz = (g & 3) << 2;
#pragma unroll
                for (int t = 0; t < 8; t++) {
                    int kc  = t*8 + 2*c;
                    int jk  = kc >> 4;
                    int k16 = kc & 15;
                    int pp0  = ((k16 & 3) << 2) | (k16 >> 2);
                    int pp1  = (((k16+1) & 3) << 2) | ((k16+1) >> 2);
                    float* base_lo = &pw[jk*256 + g*16];
                    float* base_hi = &pw[jk*256 + (g+8)*16];
                    base_lo[pp0 ^ swz] = to_tf32(sacc[t][0]);
                    base_lo[pp1 ^ swz] = to_tf32(sacc[t][1]);
                    base_hi[pp0 ^ swz] = to_tf32(sacc[t][2]);
                    base_hi[pp1 ^ swz] = to_tf32(sacc[t][3]);
                }
            }
            __syncwarp();

            {
                const float* pw = &Ps[warp * 1024];
#pragma unroll
                for (int jk = 0; jk < 4; jk++) {
                    float4 pa0 = *(const float4*)&pw[jk*256 + g*16 + fcol];
                    float4 pa1 = *(const float4*)&pw[jk*256 + (g+8)*16 + fcol];
#pragma unroll
                    for (int t = 0; t < 8; t++) {
                        float4 vf = *(const float4*)&Vs[jk*1024 + (t*8 + g)*16 + fcol];
                        mma_tf32(oacc[t], pa0.x, pa1.x, pa0.y, pa1.y, vf.x, vf.y);
                        mma_tf32(oacc[t], pa0.z, pa1.z, pa0.w, pa1.w, vf.z, vf.w);
                    }
                }
            }
        }
    }

    float inv_lo = 1.f / l_lo;
    float inv_hi = 1.f / l_hi;
#pragma unroll
    for (int t = 0; t < 8; t++) {
        int d = t*8 + 2*c;
        float2 w0 = {oacc[t][0] * inv_lo, oacc[t][1] * inv_lo};
        float2 w1 = {oacc[t][2] * inv_hi, oacc[t][3] * inv_hi};
        *(float2*)&Ob[(size_t)row_lo * MDIM + h*64 + d] = w0;
        *(float2*)&Ob[(size_t)row_hi * MDIM + h*64 + d] = w1;
    }
}

// ---------------- LayerNorm ---------------------------------------------------
__global__ __launch_bounds__(256)
void ln_kernel(const float* __restrict__ X, const float* __restrict__ g,
               const float* __restrict__ b, float* __restrict__ Y)
{
    __shared__ float red[16];
    const int row = blockIdx.x;
    const int tid = threadIdx.x;
    float4 v = ((const float4*)(X + (size_t)row*MDIM))[tid];
    float s  = v.x + v.y + v.z + v.w;
    float sq = v.x*v.x + v.y*v.y + v.z*v.z + v.w*v.w;
#pragma unroll
    for (int off = 16; off > 0; off >>= 1) {
        s  += __shfl_xor_sync(0xffffffffu, s,  off);
        sq += __shfl_xor_sync(0xffffffffu, sq, off);
    }
    int wid = tid >> 5;
    if ((tid & 31) == 0) { red[wid] = s; red[8 + wid] = sq; }
    __syncthreads();
    if (tid < 32) {
        float ss = (tid < 8) ? red[tid] : 0.f;
        float qq = (tid < 8) ? red[8 + tid] : 0.f;
#pragma unroll
        for (int off = 4; off > 0; off >>= 1) {
            ss += __shfl_xor_sync(0xffffffffu, ss, off);
            qq += __shfl_xor_sync(0xffffffffu, qq, off);
        }
        if (tid == 0) { red[0] = ss; red[1] = qq; }
    }
    __syncthreads();
    float mu  = red[0] * (1.f/1024.f);
    float var = red[1] * (1.f/1024.f) - mu*mu;
    float rstd = rsqrtf(var + EPS);
    float4 gv = ((const float4*)g)[tid];
    float4 bv = ((const float4*)b)[tid];
    float4 y;
    y.x = (v.x - mu)*rstd*gv.x + bv.x;
    y.y = (v.y - mu)*rstd*gv.y + bv.y;
    y.z = (v.z - mu)*rstd*gv.z + bv.z;
    y.w = (v.w - mu)*rstd*gv.w + bv.w;
    ((float4*)(Y + (size_t)row*MDIM))[tid] = y;
}

// ---------------- launch ------------------------------------------------------
static void sgemm(const float* A, const float* Bp, const float* bias,
                  const float* res, float* C, int Kd, int Nn, int relu)
{
    dim3 grid(Nn/256, ROWS/128);
    tf32gemm_kernel<<<grid, 512, GEMM_SMEM>>>(A, Bp, bias, res, C, Kd, Nn, relu);
}

extern "C" void kernel_launch(void* const* d_in, const int* in_sizes, int n_in,
                              void* d_out, int out_size)
{
    const float* dec  = (const float*)d_in[0];
    const float* enc  = (const float*)d_in[1];
    const float* Wq_s = (const float*)d_in[3];
    const float* bq_s = (const float*)d_in[4];
    const float* Wk_s = (const float*)d_in[5];
    const float* bk_s = (const float*)d_in[6];
    const float* Wv_s = (const float*)d_in[7];
    const float* bv_s = (const float*)d_in[8];
    const float* Wo_s = (const float*)d_in[9];
    const float* bo_s = (const float*)d_in[10];
    const float* Wq_c = (const float*)d_in[11];
    const float* bq_c = (const float*)d_in[12];
    const float* Wk_c = (const float*)d_in[13];
    const float* bk_c = (const float*)d_in[14];
    const float* Wv_c = (const float*)d_in[15];
    const float* bv_c = (const float*)d_in[16];
    const float* Wo_c = (const float*)d_in[17];
    const float* bo_c = (const float*)d_in[18];
    const float* W1   = (const float*)d_in[19];
    const float* b1   = (const float*)d_in[20];
    const float* W2   = (const float*)d_in[21];
    const float* b2   = (const float*)d_in[22];
    const float* g1   = (const float*)d_in[23];
    const float* be1  = (const float*)d_in[24];
    const float* g2   = (const float*)d_in[25];
    const float* be2  = (const float*)d_in[26];
    const float* g3   = (const float*)d_in[27];
    const float* be3  = (const float*)d_in[28];
    float* out = (float*)d_out;

    float *wqkv_s, *bqkv_s, *wq_c, *wkv_c, *bkv_c;
    float *p_wqkv, *p_wqc, *p_wkvc, *p_wos, *p_woc, *p_w1, *p_w2;
    float *qkv, *qc, *kvc, *attn, *t1, *out2, *out4, *ffn;
    cudaGetSymbolAddress((void**)&wqkv_s, g_wqkv_s);
    cudaGetSymbolAddress((void**)&bqkv_s, g_bqkv_s);
    cudaGetSymbolAddress((void**)&wq_c,   g_wq_c);
    cudaGetSymbolAddress((void**)&wkv_c,  g_wkv_c);
    cudaGetSymbolAddress((void**)&bkv_c,  g_bkv_c);
    cudaGetSymbolAddress((void**)&p_wqkv, g_p_wqkv);
    cudaGetSymbolAddress((void**)&p_wqc,  g_p_wqc);
    cudaGetSymbolAddress((void**)&p_wkvc, g_p_wkvc);
    cudaGetSymbolAddress((void**)&p_wos,  g_p_wos);
    cudaGetSymbolAddress((void**)&p_woc,  g_p_woc);
    cudaGetSymbolAddress((void**)&p_w1,   g_p_w1);
    cudaGetSymbolAddress((void**)&p_w2,   g_p_w2);
    cudaGetSymbolAddress((void**)&qkv,    g_qkv);
    cudaGetSymbolAddress((void**)&qc,     g_qc);
    cudaGetSymbolAddress((void**)&kvc,    g_kvc);
    cudaGetSymbolAddress((void**)&attn,   g_attn);
    cudaGetSymbolAddress((void**)&t1,     g_t1);
    cudaGetSymbolAddress((void**)&out2,   g_out2);
    cudaGetSymbolAddress((void**)&out4,   g_out4);
    cudaGetSymbolAddress((void**)&ffn,    g_ffn);

    cudaFuncSetAttribute(tc_attn_kernel, cudaFuncAttributeMaxDynamicSharedMemorySize, ATT_SMEM);
    cudaFuncSetAttribute(tf32gemm_kernel, cudaFuncAttributeMaxDynamicSharedMemorySize, GEMM_SMEM);

    // 1: repack attention weights to [m][N]
    {
        dim3 grid((HH*MDIM*DD)/256, 6);
        repack_all_kernel<<<grid, 256>>>(Wq_s, Wk_s, Wv_s, Wq_c, Wk_c, Wv_c,
                                         wqkv_s, wq_c, wkv_c);
    }
    // 2: pack all weights into fragment layout (one launch)
    {
        dim3 grid((MDIM*FF/4 + 255)/256, 7);
        packW_all_kernel<<<grid, 256>>>(wqkv_s, wq_c, wkv_c, Wo_s, Wo_c, W1, W2,
                                        p_wqkv, p_wqc, p_wkvc, p_wos, p_woc, p_w1, p_w2);
    }
    // concat biases
    cudaMemcpyAsync(bqkv_s,          bq_s, MDIM*sizeof(float), cudaMemcpyDeviceToDevice);
    cudaMemcpyAsync(bqkv_s + MDIM,   bk_s, MDIM*sizeof(float), cudaMemcpyDeviceToDevice);
    cudaMemcpyAsync(bqkv_s + 2*MDIM, bv_s, MDIM*sizeof(float), cudaMemcpyDeviceToDevice);
    cudaMemcpyAsync(bkv_c,           bk_c, MDIM*sizeof(float), cudaMemcpyDeviceToDevice);
    cudaMemcpyAsync(bkv_c + MDIM,    bv_c, MDIM*sizeof(float), cudaMemcpyDeviceToDevice);

    // 3: self QKV gemm
    sgemm(dec, p_wqkv, bqkv_s, nullptr, qkv, MDIM, 3*MDIM, 0);
    // 4: cross KV gemm
    sgemm(enc, p_wkvc, bkv_c, nullptr, kvc, MDIM, 2*MDIM, 0);
    // 5: self attention
    {
        dim3 grid(SEQ/128, NB*HH);
        tc_attn_kernel<<<grid, 256, ATT_SMEM>>>(qkv, 3*MDIM,
                                                qkv + MDIM, 3*MDIM,
                                                qkv + 2*MDIM, 3*MDIM,
                                                attn, 1);
    }
    // 6: Wo_s gemm  <-- ncu profiles this launch
    sgemm(attn, p_wos, bo_s, dec, t1, MDIM, MDIM, 0);
    ln_kernel<<<ROWS, 256>>>(t1, g1, be1, out2);

    // ---- cross-attention block ----
    sgemm(out2, p_wqc, bq_c, nullptr, qc, MDIM, MDIM, 0);
    {
        dim3 grid(SEQ/128, NB*HH);
        tc_attn_kernel<<<grid, 256, ATT_SMEM>>>(qc, MDIM,
                                                kvc, 2*MDIM,
                                                kvc + MDIM, 2*MDIM,
                                                attn, 0);
    }
    sgemm(attn, p_woc, bo_c, out2, t1, MDIM, MDIM, 0);
    ln_kernel<<<ROWS, 256>>>(t1, g2, be2, out4);

    // ---- feedforward block ----
    sgemm(out4, p_w1, b1, nullptr, ffn, MDIM, FF, 1);
    sgemm(ffn, p_w2, b2, out4, t1, FF, MDIM, 0);
    ln_kernel<<<ROWS, 256>>>(t1, g3, be3, out);
}

// round 16
// speedup vs baseline: 1.5622x; 1.0512x over previous
#include <cuda_runtime.h>
#include <cuda_bf16.h>
#include <cstdint>
#include <math.h>

// Problem dims
#define NB   4
#define SEQ  1024
#define MDIM 1024
#define HH   16
#define DD   64
#define FF   4096
#define ROWS (NB*SEQ)          // 4096
#define EPS  1e-5f

// ---------------- scratch (device globals; no allocation allowed) -------------
__device__ float g_wqkv_s[MDIM*3*MDIM];   // repacked [m][3072]
__device__ float g_bqkv_s[3*MDIM];
__device__ float g_wq_c [MDIM*MDIM];
__device__ float g_wkv_c[MDIM*2*MDIM];
__device__ float g_bkv_c[2*MDIM];

// packed (fragment-layout, tf32-rounded) weights
__device__ float g_p_wqkv[MDIM*3*MDIM];
__device__ float g_p_wqc [MDIM*MDIM];
__device__ float g_p_wkvc[MDIM*2*MDIM];
__device__ float g_p_wos [MDIM*MDIM];
__device__ float g_p_woc [MDIM*MDIM];
__device__ float g_p_w1  [MDIM*FF];
__device__ float g_p_w2  [FF*MDIM];

__device__ float g_qkv [ROWS*3*MDIM];
__device__ float g_qc  [ROWS*MDIM];
__device__ float g_kvc [ROWS*2*MDIM];
__device__ float g_attn[ROWS*MDIM];
__device__ float g_t1  [ROWS*MDIM];
__device__ float g_out2[ROWS*MDIM];
__device__ float g_out4[ROWS*MDIM];
__device__ float g_ffn [ROWS*FF];

// ---------------- helpers -----------------------------------------------------
__device__ __forceinline__ float to_tf32(float x)
{
    asm("cvt.rna.tf32.f32 %0, %0;" : "+f"(x));
    return x;
}

__device__ __forceinline__ void mma_tf32(float* d,
                                         float a0, float a1, float a2, float a3,
                                         float b0, float b1)
{
    asm volatile(
        "mma.sync.aligned.m16n8k8.row.col.f32.tf32.tf32.f32 "
        "{%0,%1,%2,%3}, {%4,%5,%6,%7}, {%8,%9}, {%0,%1,%2,%3};\n"
        : "+f"(d[0]), "+f"(d[1]), "+f"(d[2]), "+f"(d[3])
        : "r"(__float_as_uint(a0)), "r"(__float_as_uint(a1)),
          "r"(__float_as_uint(a2)), "r"(__float_as_uint(a3)),
          "r"(__float_as_uint(b0)), "r"(__float_as_uint(b1)));
}

__device__ __forceinline__ uint32_t smem_u32(const void* p)
{
    uint32_t a;
    asm("{ .reg .u64 t; cvta.to.shared.u64 t, %1; cvt.u32.u64 %0, t; }"
        : "=r"(a) : "l"(p));
    return a;
}

__device__ __forceinline__ void cp16(uint32_t dst, const void* src)
{
    asm volatile("cp.async.cg.shared.global [%0], [%1], 16;"
                 :: "r"(dst), "l"(src));
}
#define CP_COMMIT() asm volatile("cp.async.commit_group;" ::: "memory")
#define CP_WAIT2()  asm volatile("cp.async.wait_group 2;" ::: "memory")

// ---------------- weight repack (attention weights -> [m][N]) -----------------
__global__ void repack_all_kernel(const float* __restrict__ Wq_s, const float* __restrict__ Wk_s,
                                  const float* __restrict__ Wv_s, const float* __restrict__ Wq_c,
                                  const float* __restrict__ Wk_c, const float* __restrict__ Wv_c,
                                  float* __restrict__ wqkv_s, float* __restrict__ wq_c,
                                  float* __restrict__ wkv_c)
{
    const float* W; float* dst; int stride, off;
    switch (blockIdx.y) {
        case 0: W = Wq_s; dst = wqkv_s; stride = 3*MDIM; off = 0;      break;
        case 1: W = Wk_s; dst = wqkv_s; stride = 3*MDIM; off = MDIM;   break;
        case 2: W = Wv_s; dst = wqkv_s; stride = 3*MDIM; off = 2*MDIM; break;
        case 3: W = Wq_c; dst = wq_c;   stride = MDIM;   off = 0;      break;
        case 4: W = Wk_c; dst = wkv_c;  stride = 2*MDIM; off = 0;      break;
        default:W = Wv_c; dst = wkv_c;  stride = 2*MDIM; off = MDIM;   break;
    }
    int idx = blockIdx.x * 256 + threadIdx.x;
    int d = idx & 63;
    int m = (idx >> 6) & (MDIM-1);
    int h = idx >> 16;
    dst[m*stride + off + h*64 + d] = W[idx];
}

// ---------------- pack all 7 W[K][N] into fragment layout (ONE launch) --------
__global__ void packW_all_kernel(const float* __restrict__ wqkv, const float* __restrict__ wqc,
                                 const float* __restrict__ wkvc, const float* __restrict__ wos,
                                 const float* __restrict__ woc, const float* __restrict__ w1,
                                 const float* __restrict__ w2,
                                 float* __restrict__ p_wqkv, float* __restrict__ p_wqc,
                                 float* __restrict__ p_wkvc, float* __restrict__ p_wos,
                                 float* __restrict__ p_woc, float* __restrict__ p_w1,
                                 float* __restrict__ p_w2)
{
    const float* W; float* Wp; int K, N;
    switch (blockIdx.y) {
        case 0: W = wqkv; Wp = p_wqkv; K = MDIM; N = 3*MDIM; break;
        case 1: W = wqc;  Wp = p_wqc;  K = MDIM; N = MDIM;   break;
        case 2: W = wkvc; Wp = p_wkvc; K = MDIM; N = 2*MDIM; break;
        case 3: W = wos;  Wp = p_wos;  K = MDIM; N = MDIM;   break;
        case 4: W = woc;  Wp = p_woc;  K = MDIM; N = MDIM;   break;
        case 5: W = w1;   Wp = p_w1;   K = MDIM; N = FF;     break;
        default:W = w2;   Wp = p_w2;   K = FF;   N = MDIM;   break;
    }
    int idx = blockIdx.x * 256 + threadIdx.x;
    if (idx >= (K >> 2) * N) return;
    int j = idx & 3;
    int q = idx >> 2;
    int n = q % N;
    int kb = q / N;
    int kb16 = kb * 16 + (j ^ (n & 3));
    float4 v;
    v.x = to_tf32(W[(size_t)(kb16 +  0) * N + n]);
    v.y = to_tf32(W[(size_t)(kb16 +  4) * N + n]);
    v.z = to_tf32(W[(size_t)(kb16 +  8) * N + n]);
    v.w = to_tf32(W[(size_t)(kb16 + 12) * N + n]);
    *(float4*)&Wp[(size_t)idx * 4] = v;
}

// ===================== cp.async pipelined TF32 GEMM ===========================
// CTA 128x256, BK=16, 4 stages, 512 threads (16 warps, 32x64 warp tile).
// A fragments hoisted once per iter; t-outer loop so each inline B float4
// feeds 4 mmas. Regs ~105 < 128 cap -> room for ptxas to pipeline LDS.
#define STG_BYTES 26624           // 10240 (A, 80B rows) + 16384 (B)
#define GEMM_SMEM (4*STG_BYTES)   // 106496

__global__ __launch_bounds__(512, 1)
void tf32gemm_kernel(const float* __restrict__ A, const float* __restrict__ Bp,
                     const float* __restrict__ bias, const float* __restrict__ res,
                     float* __restrict__ C, int Kd, int Nn, int relu)
{
    extern __shared__ char smraw[];
    const uint32_t smb = smem_u32(smraw);

    const int tid  = threadIdx.x;
    const int lane = tid & 31;
    const int g    = lane >> 2;
    const int c    = lane & 3;
    const int warp = tid >> 5;            // 0..15
    const int wm   = (warp >> 2) * 32;    // 0,32,64,96
    const int wn   = (warp & 3) * 64;     // 0..192
    const int bm   = blockIdx.y * 128;
    const int bn   = blockIdx.x * 256;

    // A loader: one cp16/thread
    const int arow = tid >> 2;
    const int aq   = tid & 3;
    const float* Asrc0 = A + (size_t)(bm + arow) * Kd + aq * 4;
    // B loader: two cp16/thread
    const int bnn  = tid >> 1;
    const int bh   = tid & 1;
    const float* Bsrc0 = Bp + ((size_t)bn + bnn) * 16 + bh * 8;

    float acc[2][8][4];
#pragma unroll
    for (int i = 0; i < 2; i++)
#pragma unroll
        for (int t = 0; t < 8; t++)
#pragma unroll
            for (int r = 0; r < 4; r++) acc[i][t][r] = 0.f;

    const int iters = Kd >> 4;

    auto issue = [&](int s) {
        uint32_t base = smb + (s & 3) * STG_BYTES;
        cp16(base + arow * 80 + aq * 16, Asrc0 + s * 16);
        uint32_t bdst = base + 10240 + bnn * 64 + bh * 32;
        const float* bsrc = Bsrc0 + (size_t)s * Nn * 16;
        cp16(bdst,      bsrc);
        cp16(bdst + 16, bsrc + 4);
    };

#pragma unroll
    for (int s = 0; s < 3; s++) {
        if (s < iters) issue(s);
        CP_COMMIT();
    }

    const char* smc = (const char*)smraw;
    const uint32_t bchunk = ((uint32_t)(c ^ (g & 3))) << 4;

    for (int it = 0; it < iters; ++it) {
        CP_WAIT2();
        __syncthreads();
        if (it + 3 < iters) issue(it + 3);
        CP_COMMIT();

        const char* sA = smc + (it & 3) * STG_BYTES;
        const char* sB = sA + 10240;

        // hoist A fragments for both row groups (16 LDS.32)
        float aL[2][4], aH[2][4];
#pragma unroll
        for (int i = 0; i < 2; i++) {
            int r0 = wm + i*16 + g;
            const float* a0p = (const float*)(sA + r0 * 80);
            const float* a1p = (const float*)(sA + (r0 + 8) * 80);
#pragma unroll
            for (int j = 0; j < 4; j++) {
                aL[i][j] = a0p[c + 4*j];
                aH[i][j] = a1p[c + 4*j];
            }
        }

        // t-outer: one B float4 feeds 4 mmas
#pragma unroll
        for (int t = 0; t < 8; t++) {
            float4 bf = *(const float4*)(sB + (wn + t*8 + g) * 64 + bchunk);
            mma_tf32(acc[0][t], aL[0][0], aH[0][0], aL[0][1], aH[0][1], bf.x, bf.y);
            mma_tf32(acc[0][t], aL[0][2], aH[0][2], aL[0][3], aH[0][3], bf.z, bf.w);
            mma_tf32(acc[1][t], aL[1][0], aH[1][0], aL[1][1], aH[1][1], bf.x, bf.y);
            mma_tf32(acc[1][t], aL[1][2], aH[1][2], aL[1][3], aH[1][3], bf.z, bf.w);
        }
    }

#pragma unroll
    for (int i = 0; i < 2; i++) {
        int r0 = bm + wm + i*16 + g;
#pragma unroll
        for (int t = 0; t < 8; t++) {
            int col = bn + wn + t*8 + 2*c;
            float2 bv = *(const float2*)&bias[col];
            float v0 = acc[i][t][0] + bv.x;
            float v1 = acc[i][t][1] + bv.y;
            float v2 = acc[i][t][2] + bv.x;
            float v3 = acc[i][t][3] + bv.y;
            size_t o0 = (size_t)r0 * Nn + col;
            size_t o1 = (size_t)(r0 + 8) * Nn + col;
            if (res) {
                float2 r0v = *(const float2*)&res[o0];
                float2 r1v = *(const float2*)&res[o1];
                v0 += r0v.x; v1 += r0v.y; v2 += r1v.x; v3 += r1v.y;
            }
            if (relu) {
                v0 = fmaxf(v0, 0.f); v1 = fmaxf(v1, 0.f);
                v2 = fmaxf(v2, 0.f); v3 = fmaxf(v3, 0.f);
            }
            float2 w0 = {v0, v1};
            float2 w1 = {v2, v3};
            *(float2*)&C[o0] = w0;
            *(float2*)&C[o1] = w1;
        }
    }
}

// ===================== TF32 tensor-core flash attention =======================
// 128 q-rows per CTA (8 warps x 16 rows), key blocks of 64, D=64.
#define ATT_SMEM 98304

__global__ __launch_bounds__(256)
void tc_attn_kernel(const float* __restrict__ Qb, int sQ,
                    const float* __restrict__ Kb, int sK,
                    const float* __restrict__ Vb, int sV,
                    float* __restrict__ Ob, int causal)
{
    extern __shared__ float sm[];
    float* Qs = sm;            // [4][128][16]  (8192)
    float* Ks = sm + 8192;     // [4][64][16]   (4096)
    float* Vs = sm + 12288;    // [4][64][16]   (4096)
    float* Ps = sm + 16384;    // [warp][4][16][16] (8192)

    const int qb   = blockIdx.x;
    const int nh   = blockIdx.y;
    const int n    = nh >> 4, h = nh & 15;
    const int tid  = threadIdx.x;
    const int lane = tid & 31;
    const int warp = tid >> 5;
    const int g    = lane >> 2;
    const int c    = lane & 3;
    const int wm   = warp * 16;
    const int qrow0 = n*SEQ + qb*128;
    const float scale = 0.125f;
    const int fcol = (4*c) ^ ((g & 3) << 2);

#pragma unroll
    for (int i = 0; i < 8; i++) {
        int idx = tid + i*256;
        int r   = idx >> 4;
        int d0  = (idx & 15) * 4;
        float4 v = *(const float4*)&Qb[(size_t)(qrow0 + r)*sQ + h*64 + d0];
        int j    = d0 >> 4;
        int base = (d0 & 15) >> 2;
        int swz  = (r & 3) << 2;
        float* dst = &Qs[j*2048 + r*16];
        dst[(0*4 + base) ^ swz] = to_tf32(v.x * scale);
        dst[(1*4 + base) ^ swz] = to_tf32(v.y * scale);
        dst[(2*4 + base) ^ swz] = to_tf32(v.z * scale);
        dst[(3*4 + base) ^ swz] = to_tf32(v.w * scale);
    }
    __syncthreads();

    float4 qa[4][2];
#pragma unroll
    for (int j = 0; j < 4; j++) {
        qa[j][0] = *(const float4*)&Qs[j*2048 + (wm + g)*16 + fcol];
        qa[j][1] = *(const float4*)&Qs[j*2048 + (wm + 8 + g)*16 + fcol];
    }

    float m_lo = -1e30f, m_hi = -1e30f, l_lo = 0.f, l_hi = 0.f;
    float oacc[8][4];
#pragma unroll
    for (int t = 0; t < 8; t++)
#pragma unroll
        for (int r = 0; r < 4; r++) oacc[t][r] = 0.f;

    const int row_lo = qrow0 + wm + g;
    const int row_hi = row_lo + 8;
    const int nkb = causal ? (2*qb + 2) : (SEQ/64);

    for (int kb = 0; kb < nkb; kb++) {
        const int krow0 = n*SEQ + kb*64;
        __syncthreads();

#pragma unroll
        for (int i = 0; i < 4; i++) {
            int idx = tid + i*256;
            int r   = idx >> 4;
            int d0  = (idx & 15) * 4;
            float4 kv = *(const float4*)&Kb[(size_t)(krow0 + r)*sK + h*64 + d0];
            int j    = d0 >> 4;
            int base = (d0 & 15) >> 2;
            int swz  = (r & 3) << 2;
            float* dst = &Ks[j*1024 + r*16];
            dst[(0*4 + base) ^ swz] = to_tf32(kv.x);
            dst[(1*4 + base) ^ swz] = to_tf32(kv.y);
            dst[(2*4 + base) ^ swz] = to_tf32(kv.z);
            dst[(3*4 + base) ^ swz] = to_tf32(kv.w);

            float4 vv = *(const float4*)&Vb[(size_t)(krow0 + r)*sV + h*64 + d0];
            int jk    = r >> 4;
            int k16   = r & 15;
            int kperm = (k16 & 3)*4 + (k16 >> 2);
            float* vdst = &Vs[jk*1024];
            vdst[(d0+0)*16 + (kperm ^  0)] = to_tf32(vv.x);
            vdst[(d0+1)*16 + (kperm ^  4)] = to_tf32(vv.y);
            vdst[(d0+2)*16 + (kperm ^  8)] = to_tf32(vv.z);
            vdst[(d0+3)*16 + (kperm ^ 12)] = to_tf32(vv.w);
        }
        __syncthreads();

        const bool active = !(causal && kb == 2*qb + 1 && warp < 4);
        if (active) {
            float sacc[8][4];
#pragma unroll
            for (int t = 0; t < 8; t++)
#pragma unroll
                for (int r = 0; r < 4; r++) sacc[t][r] = 0.f;

#pragma unroll
            for (int j = 0; j < 4; j++) {
                float4 a0v = qa[j][0], a1v = qa[j][1];
#pragma unroll
                for (int t = 0; t < 8; t++) {
                    float4 bf = *(const float4*)&Ks[j*1024 + (t*8 + g)*16 + fcol];
                    mma_tf32(sacc[t], a0v.x, a1v.x, a0v.y, a1v.y, bf.x, bf.y);
                    mma_tf32(sacc[t], a0v.z, a1v.z, a0v.w, a1v.w, bf.z, bf.w);
                }
            }

            if (causal && kb >= 2*qb) {
#pragma unroll
                for (int t = 0; t < 8; t++) {
                    int col0 = krow0 + t*8 + 2*c;
                    if (col0     > row_lo) sacc[t][0] = -1e30f;
                    if (col0 + 1 > row_lo) sacc[t][1] = -1e30f;
                    if (col0     > row_hi) sacc[t][2] = -1e30f;
                    if (col0 + 1 > row_hi) sacc[t][3] = -1e30f;
                }
            }

            float mx_lo = -1e30f, mx_hi = -1e30f;
#pragma unroll
            for (int t = 0; t < 8; t++) {
                mx_lo = fmaxf(mx_lo, fmaxf(sacc[t][0], sacc[t][1]));
                mx_hi = fmaxf(mx_hi, fmaxf(sacc[t][2], sacc[t][3]));
            }
            mx_lo = fmaxf(mx_lo, __shfl_xor_sync(0xffffffffu, mx_lo, 1));
            mx_lo = fmaxf(mx_lo, __shfl_xor_sync(0xffffffffu, mx_lo, 2));
            mx_hi = fmaxf(mx_hi, __shfl_xor_sync(0xffffffffu, mx_hi, 1));
            mx_hi = fmaxf(mx_hi, __shfl_xor_sync(0xffffffffu, mx_hi, 2));

            float mn_lo = fmaxf(m_lo, mx_lo);
            float mn_hi = fmaxf(m_hi, mx_hi);
            float al_lo = __expf(m_lo - mn_lo);
            float al_hi = __expf(m_hi - mn_hi);

            float sum_lo = 0.f, sum_hi = 0.f;
#pragma unroll
            for (int t = 0; t < 8; t++) {
                sacc[t][0] = __expf(sacc[t][0] - mn_lo);
                sacc[t][1] = __expf(sacc[t][1] - mn_lo);
                sacc[t][2] = __expf(sacc[t][2] - mn_hi);
                sacc[t][3] = __expf(sacc[t][3] - mn_hi);
                sum_lo += sacc[t][0] + sacc[t][1];
                sum_hi += sacc[t][2] + sacc[t][3];
            }
            sum_lo += __shfl_xor_sync(0xffffffffu, sum_lo, 1);
            sum_lo += __shfl_xor_sync(0xffffffffu, sum_lo, 2);
            sum_hi += __shfl_xor_sync(0xffffffffu, sum_hi, 1);
            sum_hi += __shfl_xor_sync(0xffffffffu, sum_hi, 2);

            l_lo = l_lo * al_lo + sum_lo;
            l_hi = l_hi * al_hi + sum_hi;
            m_lo = mn_lo;
            m_hi = mn_hi;
#pragma unroll
            for (int t = 0; t < 8; t++) {
                oacc[t][0] *= al_lo; oacc[t][1] *= al_lo;
                oacc[t][2] *= al_hi; oacc[t][3] *= al_hi;
            }

            {
                float* pw = &Ps[warp * 1024];
                const int swz = (g & 3) << 2;
#pragma unroll
                for (int t = 0; t < 8; t++) {
                    int kc  = t*8 + 2*c;
                    int jk  = kc >> 4;
                    int k16 = kc & 15;
                    int pp0  = ((k16 & 3) << 2) | (k16 >> 2);
                    int pp1  = (((k16+1) & 3) << 2) | ((k16+1) >> 2);
                    float* base_lo = &pw[jk*256 + g*16];
                    float* base_hi = &pw[jk*256 + (g+8)*16];
                    base_lo[pp0 ^ swz] = to_tf32(sacc[t][0]);
                    base_lo[pp1 ^ swz] = to_tf32(sacc[t][1]);
                    base_hi[pp0 ^ swz] = to_tf32(sacc[t][2]);
                    base_hi[pp1 ^ swz] = to_tf32(sacc[t][3]);
                }
            }
            __syncwarp();

            {
                const float* pw = &Ps[warp * 1024];
#pragma unroll
                for (int jk = 0; jk < 4; jk++) {
                    float4 pa0 = *(const float4*)&pw[jk*256 + g*16 + fcol];
                    float4 pa1 = *(const float4*)&pw[jk*256 + (g+8)*16 + fcol];
#pragma unroll
                    for (int t = 0; t < 8; t++) {
                        float4 vf = *(const float4*)&Vs[jk*1024 + (t*8 + g)*16 + fcol];
                        mma_tf32(oacc[t], pa0.x, pa1.x, pa0.y, pa1.y, vf.x, vf.y);
                        mma_tf32(oacc[t], pa0.z, pa1.z, pa0.w, pa1.w, vf.z, vf.w);
                    }
                }
            }
        }
    }

    float inv_lo = 1.f / l_lo;
    float inv_hi = 1.f / l_hi;
#pragma unroll
    for (int t = 0; t < 8; t++) {
        int d = t*8 + 2*c;
        float2 w0 = {oacc[t][0] * inv_lo, oacc[t][1] * inv_lo};
        float2 w1 = {oacc[t][2] * inv_hi, oacc[t][3] * inv_hi};
        *(float2*)&Ob[(size_t)row_lo * MDIM + h*64 + d] = w0;
        *(float2*)&Ob[(size_t)row_hi * MDIM + h*64 + d] = w1;
    }
}

// ---------------- LayerNorm ---------------------------------------------------
__global__ __launch_bounds__(256)
void ln_kernel(const float* __restrict__ X, const float* __restrict__ g,
               const float* __restrict__ b, float* __restrict__ Y)
{
    __shared__ float red[16];
    const int row = blockIdx.x;
    const int tid = threadIdx.x;
    float4 v = ((const float4*)(X + (size_t)row*MDIM))[tid];
    float s  = v.x + v.y + v.z + v.w;
    float sq = v.x*v.x + v.y*v.y + v.z*v.z + v.w*v.w;
#pragma unroll
    for (int off = 16; off > 0; off >>= 1) {
        s  += __shfl_xor_sync(0xffffffffu, s,  off);
        sq += __shfl_xor_sync(0xffffffffu, sq, off);
    }
    int wid = tid >> 5;
    if ((tid & 31) == 0) { red[wid] = s; red[8 + wid] = sq; }
    __syncthreads();
    if (tid < 32) {
        float ss = (tid < 8) ? red[tid] : 0.f;
        float qq = (tid < 8) ? red[8 + tid] : 0.f;
#pragma unroll
        for (int off = 4; off > 0; off >>= 1) {
            ss += __shfl_xor_sync(0xffffffffu, ss, off);
            qq += __shfl_xor_sync(0xffffffffu, qq, off);
        }
        if (tid == 0) { red[0] = ss; red[1] = qq; }
    }
    __syncthreads();
    float mu  = red[0] * (1.f/1024.f);
    float var = red[1] * (1.f/1024.f) - mu*mu;
    float rstd = rsqrtf(var + EPS);
    float4 gv = ((const float4*)g)[tid];
    float4 bv = ((const float4*)b)[tid];
    float4 y;
    y.x = (v.x - mu)*rstd*gv.x + bv.x;
    y.y = (v.y - mu)*rstd*gv.y + bv.y;
    y.z = (v.z - mu)*rstd*gv.z + bv.z;
    y.w = (v.w - mu)*rstd*gv.w + bv.w;
    ((float4*)(Y + (size_t)row*MDIM))[tid] = y;
}

// ---------------- launch ------------------------------------------------------
static void sgemm(const float* A, const float* Bp, const float* bias,
                  const float* res, float* C, int Kd, int Nn, int relu)
{
    dim3 grid(Nn/256, ROWS/128);
    tf32gemm_kernel<<<grid, 512, GEMM_SMEM>>>(A, Bp, bias, res, C, Kd, Nn, relu);
}

extern "C" void kernel_launch(void* const* d_in, const int* in_sizes, int n_in,
                              void* d_out, int out_size)
{
    const float* dec  = (const float*)d_in[0];
    const float* enc  = (const float*)d_in[1];
    const float* Wq_s = (const float*)d_in[3];
    const float* bq_s = (const float*)d_in[4];
    const float* Wk_s = (const float*)d_in[5];
    const float* bk_s = (const float*)d_in[6];
    const float* Wv_s = (const float*)d_in[7];
    const float* bv_s = (const float*)d_in[8];
    const float* Wo_s = (const float*)d_in[9];
    const float* bo_s = (const float*)d_in[10];
    const float* Wq_c = (const float*)d_in[11];
    const float* bq_c = (const float*)d_in[12];
    const float* Wk_c = (const float*)d_in[13];
    const float* bk_c = (const float*)d_in[14];
    const float* Wv_c = (const float*)d_in[15];
    const float* bv_c = (const float*)d_in[16];
    const float* Wo_c = (const float*)d_in[17];
    const float* bo_c = (const float*)d_in[18];
    const float* W1   = (const float*)d_in[19];
    const float* b1   = (const float*)d_in[20];
    const float* W2   = (const float*)d_in[21];
    const float* b2   = (const float*)d_in[22];
    const float* g1   = (const float*)d_in[23];
    const float* be1  = (const float*)d_in[24];
    const float* g2   = (const float*)d_in[25];
    const float* be2  = (const float*)d_in[26];
    const float* g3   = (const float*)d_in[27];
    const float* be3  = (const float*)d_in[28];
    float* out = (float*)d_out;

    float *wqkv_s, *bqkv_s, *wq_c, *wkv_c, *bkv_c;
    float *p_wqkv, *p_wqc, *p_wkvc, *p_wos, *p_woc, *p_w1, *p_w2;
    float *qkv, *qc, *kvc, *attn, *t1, *out2, *out4, *ffn;
    cudaGetSymbolAddress((void**)&wqkv_s, g_wqkv_s);
    cudaGetSymbolAddress((void**)&bqkv_s, g_bqkv_s);
    cudaGetSymbolAddress((void**)&wq_c,   g_wq_c);
    cudaGetSymbolAddress((void**)&wkv_c,  g_wkv_c);
    cudaGetSymbolAddress((void**)&bkv_c,  g_bkv_c);
    cudaGetSymbolAddress((void**)&p_wqkv, g_p_wqkv);
    cudaGetSymbolAddress((void**)&p_wqc,  g_p_wqc);
    cudaGetSymbolAddress((void**)&p_wkvc, g_p_wkvc);
    cudaGetSymbolAddress((void**)&p_wos,  g_p_wos);
    cudaGetSymbolAddress((void**)&p_woc,  g_p_woc);
    cudaGetSymbolAddress((void**)&p_w1,   g_p_w1);
    cudaGetSymbolAddress((void**)&p_w2,   g_p_w2);
    cudaGetSymbolAddress((void**)&qkv,    g_qkv);
    cudaGetSymbolAddress((void**)&qc,     g_qc);
    cudaGetSymbolAddress((void**)&kvc,    g_kvc);
    cudaGetSymbolAddress((void**)&attn,   g_attn);
    cudaGetSymbolAddress((void**)&t1,     g_t1);
    cudaGetSymbolAddress((void**)&out2,   g_out2);
    cudaGetSymbolAddress((void**)&out4,   g_out4);
    cudaGetSymbolAddress((void**)&ffn,    g_ffn);

    cudaFuncSetAttribute(tc_attn_kernel, cudaFuncAttributeMaxDynamicSharedMemorySize, ATT_SMEM);
    cudaFuncSetAttribute(tf32gemm_kernel, cudaFuncAttributeMaxDynamicSharedMemorySize, GEMM_SMEM);

    // 1: repack attention weights to [m][N]
    {
        dim3 grid((HH*MDIM*DD)/256, 6);
        repack_all_kernel<<<grid, 256>>>(Wq_s, Wk_s, Wv_s, Wq_c, Wk_c, Wv_c,
                                         wqkv_s, wq_c, wkv_c);
    }
    // 2: pack all weights into fragment layout (one launch)
    {
        dim3 grid((MDIM*FF/4 + 255)/256, 7);
        packW_all_kernel<<<grid, 256>>>(wqkv_s, wq_c, wkv_c, Wo_s, Wo_c, W1, W2,
                                        p_wqkv, p_wqc, p_wkvc, p_wos, p_woc, p_w1, p_w2);
    }
    // concat biases
    cudaMemcpyAsync(bqkv_s,          bq_s, MDIM*sizeof(float), cudaMemcpyDeviceToDevice);
    cudaMemcpyAsync(bqkv_s + MDIM,   bk_s, MDIM*sizeof(float), cudaMemcpyDeviceToDevice);
    cudaMemcpyAsync(bqkv_s + 2*MDIM, bv_s, MDIM*sizeof(float), cudaMemcpyDeviceToDevice);
    cudaMemcpyAsync(bkv_c,           bk_c, MDIM*sizeof(float), cudaMemcpyDeviceToDevice);
    cudaMemcpyAsync(bkv_c + MDIM,    bv_c, MDIM*sizeof(float), cudaMemcpyDeviceToDevice);

    // 3: self QKV gemm
    sgemm(dec, p_wqkv, bqkv_s, nullptr, qkv, MDIM, 3*MDIM, 0);
    // 4: cross KV gemm
    sgemm(enc, p_wkvc, bkv_c, nullptr, kvc, MDIM, 2*MDIM, 0);
    // 5: self attention
    {
        dim3 grid(SEQ/128, NB*HH);
        tc_attn_kernel<<<grid, 256, ATT_SMEM>>>(qkv, 3*MDIM,
                                                qkv + MDIM, 3*MDIM,
                                                qkv + 2*MDIM, 3*MDIM,
                                                attn, 1);
    }
    // 6: Wo_s gemm  <-- ncu profiles this launch
    sgemm(attn, p_wos, bo_s, dec, t1, MDIM, MDIM, 0);
    ln_kernel<<<ROWS, 256>>>(t1, g1, be1, out2);

    // ---- cross-attention block ----
    sgemm(out2, p_wqc, bq_c, nullptr, qc, MDIM, MDIM, 0);
    {
        dim3 grid(SEQ/128, NB*HH);
        tc_attn_kernel<<<grid, 256, ATT_SMEM>>>(qc, MDIM,
                                                kvc, 2*MDIM,
                                                kvc + MDIM, 2*MDIM,
                                                attn, 0);
    }
    sgemm(attn, p_woc, bo_c, out2, t1, MDIM, MDIM, 0);
    ln_kernel<<<ROWS, 256>>>(t1, g2, be2, out4);

    // ---- feedforward block ----
    sgemm(out4, p_w1, b1, nullptr, ffn, MDIM, FF, 1);
    sgemm(ffn, p_w2, b2, out4, t1, FF, MDIM, 0);
    ln_kernel<<<ROWS, 256>>>(t1, g3, be3, out);
}